// round 11
// baseline (speedup 1.0000x reference)
#include <cuda_runtime.h>
#include <cfloat>

#define BB    4
#define NN    16384
#define MM    1024
#define CC    64
#define COP   64
#define COUT  128
#define KK    32
#define R2    0.25f
#define XTS   36        // X^T row stride in floats (144B)
#define WPC   4         // warps per CTA; each warp does 2 centers -> 8 centers/CTA

typedef unsigned long long ull;

// In-place packed dual-FMA: d.{lo,hi} += x.{lo,hi} * w.{lo,hi}
__device__ __forceinline__ void ffma2p(ull& d, ull x, ull w) {
    asm("fma.rn.f32x2 %0, %1, %2, %0;" : "+l"(d) : "l"(x), "l"(w));
}
__device__ __forceinline__ ull dupf(float w) {
    ull r;
    asm("mov.b64 %0, {%1, %1};" : "=l"(r) : "f"(w));
    return r;
}

__global__ __launch_bounds__(128, 4)
void pointnet_sampler_kernel(
    const float* __restrict__ positions,   // (B, N, 3)
    const float* __restrict__ features,    // (B, N, 64)
    const float* __restrict__ centers,     // (B, M, 3)
    const float* __restrict__ distances,   // (B, M, N)
    const float* __restrict__ W_op,        // (67, 64): rows 0..2 rel, 3..66 feat
    const float* __restrict__ b_op,        // (64)
    const float* __restrict__ W_agg,       // (64, 128)
    const float* __restrict__ b_agg,       // (128)
    float* __restrict__ out)               // (B, M, 128)
{
    const int tid  = threadIdx.x;
    const int lane = tid & 31;
    const int wid  = tid >> 5;
    const int gw0  = blockIdx.x * (2 * WPC) + 2 * wid;  // first of this warp's 2 centers
    const int b    = gw0 >> 10;
    const int m0   = gw0 & (MM - 1);
    const int ktg  = lane >> 3;                // k-tile: k in [8ktg, 8ktg+8)
    const int ct   = lane & 7;                 // c-tile: c in [8ct, 8ct+8)

    // X^T layout identical to R8 (even-XOR swizzle on feature cols)
    __shared__ __align__(16) float s_XT[WPC][67][XTS];
    __shared__ int   s_idx[WPC][KK];
    __shared__ __align__(16) float s_dist[WPC][256];
    __shared__ float s_pool[COP][10];          // cols 0..7 = centers, 8..9 pad

    // ---- prefetch center-1 distances into smem (no registers consumed) ----
    {
        const float* drow1 = distances + ((size_t)b * MM + m0 + 1) * NN;
        unsigned sdst = (unsigned)__cvta_generic_to_shared(&s_dist[wid][4 * lane]);
        asm volatile("cp.async.ca.shared.global [%0], [%1], 16;"
                     :: "r"(sdst), "l"(drow1 + 4 * lane));
        asm volatile("cp.async.ca.shared.global [%0], [%1], 16;"
                     :: "r"(sdst + 512), "l"(drow1 + 128 + 4 * lane));
        asm volatile("cp.async.commit_group;" ::: "memory");
    }

    for (int it = 0; it < 2; it++) {
        const int m = m0 + it;
        const float* drow = distances + ((size_t)b * MM + m) * NN;

        // ---- Phase A: ball query (warp-local) ----
        float dv[8];
        if (it == 0) {
#pragma unroll
            for (int j = 0; j < 8; j++) dv[j] = drow[j * 32 + lane];
        } else {
            asm volatile("cp.async.wait_group 0;" ::: "memory");
            __syncwarp();
#pragma unroll
            for (int j = 0; j < 8; j++) dv[j] = s_dist[wid][j * 32 + lane];
        }

        int count = 0;
#pragma unroll
        for (int j = 0; j < 8; j++) {
            if (count < KK) {                  // warp-uniform
                bool v = dv[j] < R2;
                unsigned msk = __ballot_sync(0xffffffffu, v);
                int pre = __popc(msk & ((1u << lane) - 1u));
                if (v && count + pre < KK) s_idx[wid][count + pre] = j * 32 + lane;
                count += __popc(msk);
            }
        }
        int base = 256;
        while (count < KK && base < NN) {      // rare fallback (~1% of rows)
            float d = drow[base + lane];
            bool v = d < R2;
            unsigned msk = __ballot_sync(0xffffffffu, v);
            int pre = __popc(msk & ((1u << lane) - 1u));
            if (v && count + pre < KK) s_idx[wid][count + pre] = base + lane;
            count += __popc(msk);
            base += 32;
        }
        const int V = min(count, KK);          // warp-uniform
        __syncwarp();

        // ---- rel-pos rows 0..2 (col = k, no swizzle) ----
        if (lane < V) {
            const float* cp = centers   + ((size_t)b * MM + m) * 3;
            const float* pp = positions + ((size_t)b * NN + s_idx[wid][lane]) * 3;
            s_XT[wid][0][lane] = pp[0] - cp[0];
            s_XT[wid][1][lane] = pp[1] - cp[1];
            s_XT[wid][2][lane] = pp[2] - cp[2];
        }

        // ---- feature gather: coalesced loads, swizzled transposed scatter ----
        {
            const float* featb = features + (size_t)b * NN * CC;
            const int c16 = lane & 15;
            const int khalf = lane >> 4;
#pragma unroll
            for (int jb = 0; jb < 4; jb++) {
                float4 v[4];
                int kk[4];
#pragma unroll
                for (int jj = 0; jj < 4; jj++) {
                    int j = 4 * jb + jj;
                    int k = 2 * j + khalf;
                    kk[jj] = k;
                    int id = (k < V) ? s_idx[wid][k] : 0;
                    v[jj] = *reinterpret_cast<const float4*>(
                        featb + (size_t)id * CC + c16 * 4);
                }
#pragma unroll
                for (int jj = 0; jj < 4; jj++) {
                    int k = kk[jj];
                    int kcol = (k & 3) + 4 * ((k >> 2) ^ (c16 & 6));
                    int r0 = 3 + 4 * c16;
                    s_XT[wid][r0 + 0][kcol] = v[jj].x;
                    s_XT[wid][r0 + 1][kcol] = v[jj].y;
                    s_XT[wid][r0 + 2][kcol] = v[jj].z;
                    s_XT[wid][r0 + 3][kcol] = v[jj].w;
                }
            }
        }
        __syncwarp();

        // ---- Phase B: 8k x 8c register-tiled GEMM (along-k f32x2 pairs) ----
        ull acc[4][8];
#pragma unroll
        for (int p = 0; p < 4; p++)
#pragma unroll
            for (int c = 0; c < 8; c++) acc[p][c] = 0ull;

        const float* xtw = &s_XT[wid][0][0];
        const float* wop = W_op + 8 * ct;

#pragma unroll 2
        for (int ib = 0; ib < 16; ib++) {
            const int colf = 4 * ((2 * ktg) ^ (ib & 6));
#pragma unroll
            for (int rr = 0; rr < 4; rr++) {
                const int row = 3 + 4 * ib + rr;
                const float* xr = xtw + row * XTS + colf;
                ulonglong2 xA = *reinterpret_cast<const ulonglong2*>(xr);
                ulonglong2 xB = *reinterpret_cast<const ulonglong2*>(xr + 4);
                float4 wA = __ldg(reinterpret_cast<const float4*>(wop + (size_t)row * COP));
                float4 wB = __ldg(reinterpret_cast<const float4*>(wop + (size_t)row * COP + 4));
                ull w0 = dupf(wA.x), w1 = dupf(wA.y), w2 = dupf(wA.z), w3 = dupf(wA.w);
                ull w4 = dupf(wB.x), w5 = dupf(wB.y), w6 = dupf(wB.z), w7 = dupf(wB.w);
                ffma2p(acc[0][0], xA.x, w0); ffma2p(acc[1][0], xA.y, w0);
                ffma2p(acc[2][0], xB.x, w0); ffma2p(acc[3][0], xB.y, w0);
                ffma2p(acc[0][1], xA.x, w1); ffma2p(acc[1][1], xA.y, w1);
                ffma2p(acc[2][1], xB.x, w1); ffma2p(acc[3][1], xB.y, w1);
                ffma2p(acc[0][2], xA.x, w2); ffma2p(acc[1][2], xA.y, w2);
                ffma2p(acc[2][2], xB.x, w2); ffma2p(acc[3][2], xB.y, w2);
                ffma2p(acc[0][3], xA.x, w3); ffma2p(acc[1][3], xA.y, w3);
                ffma2p(acc[2][3], xB.x, w3); ffma2p(acc[3][3], xB.y, w3);
                ffma2p(acc[0][4], xA.x, w4); ffma2p(acc[1][4], xA.y, w4);
                ffma2p(acc[2][4], xB.x, w4); ffma2p(acc[3][4], xB.y, w4);
                ffma2p(acc[0][5], xA.x, w5); ffma2p(acc[1][5], xA.y, w5);
                ffma2p(acc[2][5], xB.x, w5); ffma2p(acc[3][5], xB.y, w5);
                ffma2p(acc[0][6], xA.x, w6); ffma2p(acc[1][6], xA.y, w6);
                ffma2p(acc[2][6], xB.x, w6); ffma2p(acc[3][6], xB.y, w6);
                ffma2p(acc[0][7], xA.x, w7); ffma2p(acc[1][7], xA.y, w7);
                ffma2p(acc[2][7], xB.x, w7); ffma2p(acc[3][7], xB.y, w7);
            }
        }
        // rel tail: X^T rows 0..2 (cols natural), W rows 0..2
#pragma unroll
        for (int row = 0; row < 3; row++) {
            const float* xr = xtw + row * XTS + 8 * ktg;
            ulonglong2 xA = *reinterpret_cast<const ulonglong2*>(xr);
            ulonglong2 xB = *reinterpret_cast<const ulonglong2*>(xr + 4);
            float4 wA = __ldg(reinterpret_cast<const float4*>(wop + (size_t)row * COP));
            float4 wB = __ldg(reinterpret_cast<const float4*>(wop + (size_t)row * COP + 4));
            ull wv[8] = { dupf(wA.x), dupf(wA.y), dupf(wA.z), dupf(wA.w),
                          dupf(wB.x), dupf(wB.y), dupf(wB.z), dupf(wB.w) };
#pragma unroll
            for (int c = 0; c < 8; c++) {
                ffma2p(acc[0][c], xA.x, wv[c]); ffma2p(acc[1][c], xA.y, wv[c]);
                ffma2p(acc[2][c], xB.x, wv[c]); ffma2p(acc[3][c], xB.y, wv[c]);
            }
        }

        // ---- bias + masked max over this thread's 8 k's, reduce over ktg ----
        {
            float4 bA = __ldg(reinterpret_cast<const float4*>(b_op + 8 * ct));
            float4 bB = __ldg(reinterpret_cast<const float4*>(b_op + 8 * ct + 4));
            const float bv[8] = { bA.x, bA.y, bA.z, bA.w, bB.x, bB.y, bB.z, bB.w };
            float mx[8];
#pragma unroll
            for (int c = 0; c < 8; c++) mx[c] = -FLT_MAX;
#pragma unroll
            for (int p = 0; p < 4; p++) {
                bool vlo = (8 * ktg + 2 * p)     < V;
                bool vhi = (8 * ktg + 2 * p + 1) < V;
#pragma unroll
                for (int c = 0; c < 8; c++) {
                    float2 f = *reinterpret_cast<float2*>(&acc[p][c]);
                    if (vlo) mx[c] = fmaxf(mx[c], f.x + bv[c]);
                    if (vhi) mx[c] = fmaxf(mx[c], f.y + bv[c]);
                }
            }
#pragma unroll
            for (int d = 8; d < 32; d <<= 1)
#pragma unroll
                for (int c = 0; c < 8; c++)
                    mx[c] = fmaxf(mx[c], __shfl_xor_sync(0xffffffffu, mx[c], d));
            float z = (V < KK) ? 0.f : -FLT_MAX;
            if (ktg == 0) {                    // lanes 0..7
#pragma unroll
                for (int c = 0; c < 8; c++)
                    s_pool[8 * ct + c][2 * wid + it] = fmaxf(mx[c], z);
            }
        }
        __syncwarp();
    }
    __syncthreads();

    // ---- Phase C: cooperative aggregator, 8 centers share each W_agg read ----
    {
        ull a01 = dupf(b_agg[tid]);
        ull a23 = a01, a45 = a01, a67 = a01;
#pragma unroll 8
        for (int cc = 0; cc < COP; cc++) {
            ull wd = dupf(__ldg(&W_agg[(size_t)cc * COUT + tid]));
            const float* pr = &s_pool[cc][0];
            ull p01 = *reinterpret_cast<const ull*>(pr + 0);
            ull p23 = *reinterpret_cast<const ull*>(pr + 2);
            ull p45 = *reinterpret_cast<const ull*>(pr + 4);
            ull p67 = *reinterpret_cast<const ull*>(pr + 6);
            ffma2p(a01, p01, wd);
            ffma2p(a23, p23, wd);
            ffma2p(a45, p45, wd);
            ffma2p(a67, p67, wd);
        }
        float2 r01 = *reinterpret_cast<float2*>(&a01);
        float2 r23 = *reinterpret_cast<float2*>(&a23);
        float2 r45 = *reinterpret_cast<float2*>(&a45);
        float2 r67 = *reinterpret_cast<float2*>(&a67);
        const int mb = (blockIdx.x * (2 * WPC)) & (MM - 1);
        size_t obase = ((size_t)b * MM + mb) * COUT + tid;
        out[obase + 0 * COUT] = fmaxf(r01.x, 0.f);
        out[obase + 1 * COUT] = fmaxf(r01.y, 0.f);
        out[obase + 2 * COUT] = fmaxf(r23.x, 0.f);
        out[obase + 3 * COUT] = fmaxf(r23.y, 0.f);
        out[obase + 4 * COUT] = fmaxf(r45.x, 0.f);
        out[obase + 5 * COUT] = fmaxf(r45.y, 0.f);
        out[obase + 6 * COUT] = fmaxf(r67.x, 0.f);
        out[obase + 7 * COUT] = fmaxf(r67.y, 0.f);
    }
}

extern "C" void kernel_launch(void* const* d_in, const int* in_sizes, int n_in,
                              void* d_out, int out_size)
{
    (void)in_sizes; (void)n_in; (void)out_size;
    pointnet_sampler_kernel<<<BB * MM / (2 * WPC), 128>>>(
        (const float*)d_in[0],  // positions
        (const float*)d_in[1],  // features
        (const float*)d_in[2],  // centers
        (const float*)d_in[3],  // distances
        (const float*)d_in[4],  // W_op
        (const float*)d_in[5],  // b_op
        (const float*)d_in[6],  // W_agg
        (const float*)d_in[7],  // b_agg
        (float*)d_out);
}

// round 12
// speedup vs baseline: 1.2402x; 1.2402x over previous
#include <cuda_runtime.h>
#include <cfloat>

#define BB    4
#define NN    16384
#define MM    1024
#define CC    64
#define COP   64
#define COUT  128
#define KK    32
#define R2    0.25f
#define XTS   36        // X^T row stride in floats (144B)
#define WPC   4         // warps (= centers) per CTA

typedef unsigned long long ull;

// In-place packed dual-FMA: d.{lo,hi} += x.{lo,hi} * w.{lo,hi}
__device__ __forceinline__ void ffma2p(ull& d, ull x, ull w) {
    asm("fma.rn.f32x2 %0, %1, %2, %0;" : "+l"(d) : "l"(x), "l"(w));
}
__device__ __forceinline__ ull dupf(float w) {
    ull r;
    asm("mov.b64 %0, {%1, %1};" : "=l"(r) : "f"(w));
    return r;
}

__global__ __launch_bounds__(128, 5)
void pointnet_sampler_kernel(
    const float* __restrict__ positions,   // (B, N, 3)
    const float* __restrict__ features,    // (B, N, 64)
    const float* __restrict__ centers,     // (B, M, 3)
    const float* __restrict__ distances,   // (B, M, N)
    const float* __restrict__ W_op,        // (67, 64): rows 0..2 rel, 3..66 feat
    const float* __restrict__ b_op,        // (64)
    const float* __restrict__ W_agg,       // (64, 128)
    const float* __restrict__ b_agg,       // (128)
    float* __restrict__ out)               // (B, M, 128)
{
    const int tid  = threadIdx.x;
    const int lane = tid & 31;
    const int wid  = tid >> 5;
    const int gw   = blockIdx.x * WPC + wid;   // global center index (0..4095)
    const int b    = gw >> 10;
    const int m    = gw & (MM - 1);
    const int ktg  = lane >> 3;                // k-tile: k in [8ktg, 8ktg+8)
    const int ct   = lane & 7;                 // c-tile: c in [8ct, 8ct+8)

    // X^T[i][col]: rows 0..2 = rel (col = k), rows 3+4*c16+rr = features,
    // feature col = (k&3) + 4*((k>>2) ^ (c16&6))  (even-XOR swizzle)
    __shared__ __align__(16) float s_XT[WPC][67][XTS];
    __shared__ int   s_idx[WPC][KK];
    __shared__ float s_pool[COP][6];   // [cc][g0 g1 g2 g3 pad pad]

    // ---- Phase A: ball query (warp-local) ----
    const float* drow = distances + ((size_t)b * MM + m) * NN;
    float dv[8];
#pragma unroll
    for (int j = 0; j < 8; j++) dv[j] = drow[j * 32 + lane];

    int count = 0;
#pragma unroll
    for (int j = 0; j < 8; j++) {
        if (count < KK) {                      // warp-uniform
            bool v = dv[j] < R2;
            unsigned msk = __ballot_sync(0xffffffffu, v);
            int pre = __popc(msk & ((1u << lane) - 1u));
            if (v && count + pre < KK) s_idx[wid][count + pre] = j * 32 + lane;
            count += __popc(msk);
        }
    }
    int base = 256;
    while (count < KK && base < NN) {          // rare fallback (~1% of rows)
        float d = drow[base + lane];
        bool v = d < R2;
        unsigned msk = __ballot_sync(0xffffffffu, v);
        int pre = __popc(msk & ((1u << lane) - 1u));
        if (v && count + pre < KK) s_idx[wid][count + pre] = base + lane;
        count += __popc(msk);
        base += 32;
    }
    const int V = min(count, KK);              // warp-uniform
    __syncwarp();

    // ---- rel-pos rows 0..2 (col = k, no swizzle) ----
    if (lane < V) {
        const float* cp = centers   + ((size_t)b * MM + m) * 3;
        const float* pp = positions + ((size_t)b * NN + s_idx[wid][lane]) * 3;
        s_XT[wid][0][lane] = pp[0] - cp[0];
        s_XT[wid][1][lane] = pp[1] - cp[1];
        s_XT[wid][2][lane] = pp[2] - cp[2];
    }

    // ---- feature gather: coalesced loads, swizzled transposed scatter ----
    {
        const float* featb = features + (size_t)b * NN * CC;
        const int c16 = lane & 15;
        const int khalf = lane >> 4;
#pragma unroll
        for (int jb = 0; jb < 4; jb++) {
            float4 v[4];
            int kk[4];
#pragma unroll
            for (int jj = 0; jj < 4; jj++) {
                int j = 4 * jb + jj;
                int k = 2 * j + khalf;
                kk[jj] = k;
                int id = (k < V) ? s_idx[wid][k] : 0;
                v[jj] = *reinterpret_cast<const float4*>(
                    featb + (size_t)id * CC + c16 * 4);
            }
#pragma unroll
            for (int jj = 0; jj < 4; jj++) {
                int k = kk[jj];
                int kcol = (k & 3) + 4 * ((k >> 2) ^ (c16 & 6));
                int r0 = 3 + 4 * c16;
                s_XT[wid][r0 + 0][kcol] = v[jj].x;
                s_XT[wid][r0 + 1][kcol] = v[jj].y;
                s_XT[wid][r0 + 2][kcol] = v[jj].z;
                s_XT[wid][r0 + 3][kcol] = v[jj].w;
            }
        }
    }
    __syncwarp();

    // ---- Phase B: 8k x 8c register-tiled GEMM (along-k f32x2 pairs) ----
    ull acc[4][8];
#pragma unroll
    for (int p = 0; p < 4; p++)
#pragma unroll
        for (int c = 0; c < 8; c++) acc[p][c] = 0ull;

    const float* xtw = &s_XT[wid][0][0];
    const float* wop = W_op + 8 * ct;

#pragma unroll 1
    for (int ib = 0; ib < 16; ib++) {
        const int colf = 4 * ((2 * ktg) ^ (ib & 6));
#pragma unroll
        for (int rr = 0; rr < 4; rr++) {
            const int row = 3 + 4 * ib + rr;
            const float* xr = xtw + row * XTS + colf;
            ulonglong2 xA = *reinterpret_cast<const ulonglong2*>(xr);
            ulonglong2 xB = *reinterpret_cast<const ulonglong2*>(xr + 4);
            float4 wA = __ldg(reinterpret_cast<const float4*>(wop + (size_t)row * COP));
            float4 wB = __ldg(reinterpret_cast<const float4*>(wop + (size_t)row * COP + 4));
            ull w0 = dupf(wA.x), w1 = dupf(wA.y), w2 = dupf(wA.z), w3 = dupf(wA.w);
            ull w4 = dupf(wB.x), w5 = dupf(wB.y), w6 = dupf(wB.z), w7 = dupf(wB.w);
            ffma2p(acc[0][0], xA.x, w0); ffma2p(acc[1][0], xA.y, w0);
            ffma2p(acc[2][0], xB.x, w0); ffma2p(acc[3][0], xB.y, w0);
            ffma2p(acc[0][1], xA.x, w1); ffma2p(acc[1][1], xA.y, w1);
            ffma2p(acc[2][1], xB.x, w1); ffma2p(acc[3][1], xB.y, w1);
            ffma2p(acc[0][2], xA.x, w2); ffma2p(acc[1][2], xA.y, w2);
            ffma2p(acc[2][2], xB.x, w2); ffma2p(acc[3][2], xB.y, w2);
            ffma2p(acc[0][3], xA.x, w3); ffma2p(acc[1][3], xA.y, w3);
            ffma2p(acc[2][3], xB.x, w3); ffma2p(acc[3][3], xB.y, w3);
            ffma2p(acc[0][4], xA.x, w4); ffma2p(acc[1][4], xA.y, w4);
            ffma2p(acc[2][4], xB.x, w4); ffma2p(acc[3][4], xB.y, w4);
            ffma2p(acc[0][5], xA.x, w5); ffma2p(acc[1][5], xA.y, w5);
            ffma2p(acc[2][5], xB.x, w5); ffma2p(acc[3][5], xB.y, w5);
            ffma2p(acc[0][6], xA.x, w6); ffma2p(acc[1][6], xA.y, w6);
            ffma2p(acc[2][6], xB.x, w6); ffma2p(acc[3][6], xB.y, w6);
            ffma2p(acc[0][7], xA.x, w7); ffma2p(acc[1][7], xA.y, w7);
            ffma2p(acc[2][7], xB.x, w7); ffma2p(acc[3][7], xB.y, w7);
        }
    }
    // rel tail: X^T rows 0..2 (cols natural), W rows 0..2
#pragma unroll
    for (int row = 0; row < 3; row++) {
        const float* xr = xtw + row * XTS + 8 * ktg;
        ulonglong2 xA = *reinterpret_cast<const ulonglong2*>(xr);
        ulonglong2 xB = *reinterpret_cast<const ulonglong2*>(xr + 4);
        float4 wA = __ldg(reinterpret_cast<const float4*>(wop + (size_t)row * COP));
        float4 wB = __ldg(reinterpret_cast<const float4*>(wop + (size_t)row * COP + 4));
        ull wv[8] = { dupf(wA.x), dupf(wA.y), dupf(wA.z), dupf(wA.w),
                      dupf(wB.x), dupf(wB.y), dupf(wB.z), dupf(wB.w) };
#pragma unroll
        for (int c = 0; c < 8; c++) {
            ffma2p(acc[0][c], xA.x, wv[c]); ffma2p(acc[1][c], xA.y, wv[c]);
            ffma2p(acc[2][c], xB.x, wv[c]); ffma2p(acc[3][c], xB.y, wv[c]);
        }
    }

    // ---- bias + masked max over this thread's 8 k's, reduce over ktg lanes ----
    {
        float4 bA = __ldg(reinterpret_cast<const float4*>(b_op + 8 * ct));
        float4 bB = __ldg(reinterpret_cast<const float4*>(b_op + 8 * ct + 4));
        const float bv[8] = { bA.x, bA.y, bA.z, bA.w, bB.x, bB.y, bB.z, bB.w };
        float mx[8];
#pragma unroll
        for (int c = 0; c < 8; c++) mx[c] = -FLT_MAX;
#pragma unroll
        for (int p = 0; p < 4; p++) {
            bool vlo = (8 * ktg + 2 * p)     < V;
            bool vhi = (8 * ktg + 2 * p + 1) < V;
#pragma unroll
            for (int c = 0; c < 8; c++) {
                float2 f = *reinterpret_cast<float2*>(&acc[p][c]);
                if (vlo) mx[c] = fmaxf(mx[c], f.x + bv[c]);
                if (vhi) mx[c] = fmaxf(mx[c], f.y + bv[c]);
            }
        }
#pragma unroll
        for (int d = 8; d < 32; d <<= 1)
#pragma unroll
            for (int c = 0; c < 8; c++)
                mx[c] = fmaxf(mx[c], __shfl_xor_sync(0xffffffffu, mx[c], d));
        float z = (V < KK) ? 0.f : -FLT_MAX;   // zero row joins iff a slot invalid
        if (ktg == 0) {                        // lanes 0..7
#pragma unroll
            for (int c = 0; c < 8; c++)
                s_pool[8 * ct + c][wid] = fmaxf(mx[c], z);
        }
    }
    __syncthreads();

    // ---- Phase C: cooperative aggregator, 4 centers share each W_agg read ----
    {
        ull acc01 = dupf(b_agg[tid]);
        ull acc23 = acc01;
#pragma unroll 8
        for (int cc = 0; cc < COP; cc++) {
            ull wd  = dupf(__ldg(&W_agg[(size_t)cc * COUT + tid]));
            ull p01 = *reinterpret_cast<const ull*>(&s_pool[cc][0]);
            ull p23 = *reinterpret_cast<const ull*>(&s_pool[cc][2]);
            ffma2p(acc01, p01, wd);
            ffma2p(acc23, p23, wd);
        }
        float2 r01 = *reinterpret_cast<float2*>(&acc01);
        float2 r23 = *reinterpret_cast<float2*>(&acc23);
        const int mbase = (blockIdx.x * WPC) & (MM - 1);
        size_t obase = ((size_t)b * MM + mbase) * COUT + tid;
        out[obase + 0 * COUT] = fmaxf(r01.x, 0.f);
        out[obase + 1 * COUT] = fmaxf(r01.y, 0.f);
        out[obase + 2 * COUT] = fmaxf(r23.x, 0.f);
        out[obase + 3 * COUT] = fmaxf(r23.y, 0.f);
    }
}

extern "C" void kernel_launch(void* const* d_in, const int* in_sizes, int n_in,
                              void* d_out, int out_size)
{
    (void)in_sizes; (void)n_in; (void)out_size;
    pointnet_sampler_kernel<<<BB * MM / WPC, 128>>>(
        (const float*)d_in[0],  // positions
        (const float*)d_in[1],  // features
        (const float*)d_in[2],  // centers
        (const float*)d_in[3],  // distances
        (const float*)d_in[4],  // W_op
        (const float*)d_in[5],  // b_op
        (const float*)d_in[6],  // W_agg
        (const float*)d_in[7],  // b_agg
        (float*)d_out);
}

// round 13
// speedup vs baseline: 1.8098x; 1.4592x over previous
#include <cuda_runtime.h>
#include <cfloat>

#define BB    4
#define NN    16384
#define MM    1024
#define CC    64
#define COP   64
#define COUT  128
#define KK    32
#define R2    0.25f
#define XTS   36        // X^T row stride in floats (144B)
#define WPC   4         // warps (= centers) per CTA

typedef unsigned long long ull;

// In-place packed dual-FMA: d.{lo,hi} += x.{lo,hi} * w.{lo,hi}
__device__ __forceinline__ void ffma2p(ull& d, ull x, ull w) {
    asm("fma.rn.f32x2 %0, %1, %2, %0;" : "+l"(d) : "l"(x), "l"(w));
}
__device__ __forceinline__ ull dupf(float w) {
    ull r;
    asm("mov.b64 %0, {%1, %1};" : "=l"(r) : "f"(w));
    return r;
}

__global__ __launch_bounds__(128, 4)
void pointnet_sampler_kernel(
    const float* __restrict__ positions,   // (B, N, 3)
    const float* __restrict__ features,    // (B, N, 64)
    const float* __restrict__ centers,     // (B, M, 3)
    const float* __restrict__ distances,   // (B, M, N)
    const float* __restrict__ W_op,        // (67, 64): rows 0..2 rel, 3..66 feat
    const float* __restrict__ b_op,        // (64)
    const float* __restrict__ W_agg,       // (64, 128)
    const float* __restrict__ b_agg,       // (128)
    float* __restrict__ out)               // (B, M, 128)
{
    const int tid  = threadIdx.x;
    const int lane = tid & 31;
    const int wid  = tid >> 5;
    const int gw   = blockIdx.x * WPC + wid;   // global center index (0..4095)
    const int b    = gw >> 10;
    const int m    = gw & (MM - 1);
    const int ktg  = lane >> 3;                // k-tile: k in [8ktg, 8ktg+8)
    const int ct   = lane & 7;                 // c-tile: c in [8ct, 8ct+8)

    // X^T[i][col]: rows 0..2 = rel (col = k), rows 3+4*c16+rr = features,
    // feature col = (k&3) + 4*((k>>2) ^ (c16&6))  (even-XOR swizzle)
    __shared__ __align__(16) float s_XT[WPC][67][XTS];
    __shared__ int   s_idx[WPC][KK];
    __shared__ float s_pool[COP][6];   // [cc][g0 g1 g2 g3 pad pad]

    // ---- Phase A: ball query (warp-local) ----
    const float* drow = distances + ((size_t)b * MM + m) * NN;
    float dv[8];
#pragma unroll
    for (int j = 0; j < 8; j++) dv[j] = drow[j * 32 + lane];

    int count = 0;
#pragma unroll
    for (int j = 0; j < 8; j++) {
        if (count < KK) {                      // warp-uniform
            bool v = dv[j] < R2;
            unsigned msk = __ballot_sync(0xffffffffu, v);
            int pre = __popc(msk & ((1u << lane) - 1u));
            if (v && count + pre < KK) s_idx[wid][count + pre] = j * 32 + lane;
            count += __popc(msk);
        }
    }
    int base = 256;
    while (count < KK && base < NN) {          // rare fallback (~1% of rows)
        float d = drow[base + lane];
        bool v = d < R2;
        unsigned msk = __ballot_sync(0xffffffffu, v);
        int pre = __popc(msk & ((1u << lane) - 1u));
        if (v && count + pre < KK) s_idx[wid][count + pre] = base + lane;
        count += __popc(msk);
        base += 32;
    }
    const int V = min(count, KK);              // warp-uniform
    __syncwarp();

    // ---- rel-pos rows 0..2 (col = k, no swizzle) ----
    if (lane < V) {
        const float* cp = centers   + ((size_t)b * MM + m) * 3;
        const float* pp = positions + ((size_t)b * NN + s_idx[wid][lane]) * 3;
        s_XT[wid][0][lane] = pp[0] - cp[0];
        s_XT[wid][1][lane] = pp[1] - cp[1];
        s_XT[wid][2][lane] = pp[2] - cp[2];
    }

    // ---- feature gather: coalesced loads, swizzled transposed scatter ----
    {
        const float* featb = features + (size_t)b * NN * CC;
        const int c16 = lane & 15;
        const int khalf = lane >> 4;
#pragma unroll
        for (int jb = 0; jb < 4; jb++) {
            float4 v[4];
            int kk[4];
#pragma unroll
            for (int jj = 0; jj < 4; jj++) {
                int j = 4 * jb + jj;
                int k = 2 * j + khalf;
                kk[jj] = k;
                int id = (k < V) ? s_idx[wid][k] : 0;
                v[jj] = *reinterpret_cast<const float4*>(
                    featb + (size_t)id * CC + c16 * 4);
            }
#pragma unroll
            for (int jj = 0; jj < 4; jj++) {
                int k = kk[jj];
                int kcol = (k & 3) + 4 * ((k >> 2) ^ (c16 & 6));
                int r0 = 3 + 4 * c16;
                s_XT[wid][r0 + 0][kcol] = v[jj].x;
                s_XT[wid][r0 + 1][kcol] = v[jj].y;
                s_XT[wid][r0 + 2][kcol] = v[jj].z;
                s_XT[wid][r0 + 3][kcol] = v[jj].w;
            }
        }
    }
    __syncwarp();

    // ---- Phase B: 8k x 8c register-tiled GEMM (along-k f32x2 pairs) ----
    ull acc[4][8];
#pragma unroll
    for (int p = 0; p < 4; p++)
#pragma unroll
        for (int c = 0; c < 8; c++) acc[p][c] = 0ull;

    const float* xtw = &s_XT[wid][0][0];
    const float* wop = W_op + 8 * ct;

#pragma unroll 2
    for (int ib = 0; ib < 16; ib++) {
        const int colf = 4 * ((2 * ktg) ^ (ib & 6));
#pragma unroll
        for (int rr = 0; rr < 4; rr++) {
            const int row = 3 + 4 * ib + rr;
            const float* xr = xtw + row * XTS + colf;
            ulonglong2 xA = *reinterpret_cast<const ulonglong2*>(xr);
            ulonglong2 xB = *reinterpret_cast<const ulonglong2*>(xr + 4);
            float4 wA = __ldg(reinterpret_cast<const float4*>(wop + (size_t)row * COP));
            float4 wB = __ldg(reinterpret_cast<const float4*>(wop + (size_t)row * COP + 4));
            ull w0 = dupf(wA.x), w1 = dupf(wA.y), w2 = dupf(wA.z), w3 = dupf(wA.w);
            ull w4 = dupf(wB.x), w5 = dupf(wB.y), w6 = dupf(wB.z), w7 = dupf(wB.w);
            ffma2p(acc[0][0], xA.x, w0); ffma2p(acc[1][0], xA.y, w0);
            ffma2p(acc[2][0], xB.x, w0); ffma2p(acc[3][0], xB.y, w0);
            ffma2p(acc[0][1], xA.x, w1); ffma2p(acc[1][1], xA.y, w1);
            ffma2p(acc[2][1], xB.x, w1); ffma2p(acc[3][1], xB.y, w1);
            ffma2p(acc[0][2], xA.x, w2); ffma2p(acc[1][2], xA.y, w2);
            ffma2p(acc[2][2], xB.x, w2); ffma2p(acc[3][2], xB.y, w2);
            ffma2p(acc[0][3], xA.x, w3); ffma2p(acc[1][3], xA.y, w3);
            ffma2p(acc[2][3], xB.x, w3); ffma2p(acc[3][3], xB.y, w3);
            ffma2p(acc[0][4], xA.x, w4); ffma2p(acc[1][4], xA.y, w4);
            ffma2p(acc[2][4], xB.x, w4); ffma2p(acc[3][4], xB.y, w4);
            ffma2p(acc[0][5], xA.x, w5); ffma2p(acc[1][5], xA.y, w5);
            ffma2p(acc[2][5], xB.x, w5); ffma2p(acc[3][5], xB.y, w5);
            ffma2p(acc[0][6], xA.x, w6); ffma2p(acc[1][6], xA.y, w6);
            ffma2p(acc[2][6], xB.x, w6); ffma2p(acc[3][6], xB.y, w6);
            ffma2p(acc[0][7], xA.x, w7); ffma2p(acc[1][7], xA.y, w7);
            ffma2p(acc[2][7], xB.x, w7); ffma2p(acc[3][7], xB.y, w7);
        }
    }
    // rel tail: X^T rows 0..2 (cols natural), W rows 0..2
#pragma unroll
    for (int row = 0; row < 3; row++) {
        const float* xr = xtw + row * XTS + 8 * ktg;
        ulonglong2 xA = *reinterpret_cast<const ulonglong2*>(xr);
        ulonglong2 xB = *reinterpret_cast<const ulonglong2*>(xr + 4);
        float4 wA = __ldg(reinterpret_cast<const float4*>(wop + (size_t)row * COP));
        float4 wB = __ldg(reinterpret_cast<const float4*>(wop + (size_t)row * COP + 4));
        ull wv[8] = { dupf(wA.x), dupf(wA.y), dupf(wA.z), dupf(wA.w),
                      dupf(wB.x), dupf(wB.y), dupf(wB.z), dupf(wB.w) };
#pragma unroll
        for (int c = 0; c < 8; c++) {
            ffma2p(acc[0][c], xA.x, wv[c]); ffma2p(acc[1][c], xA.y, wv[c]);
            ffma2p(acc[2][c], xB.x, wv[c]); ffma2p(acc[3][c], xB.y, wv[c]);
        }
    }

    // ---- bias + masked max over this thread's 8 k's, reduce over ktg lanes ----
    {
        float4 bA = __ldg(reinterpret_cast<const float4*>(b_op + 8 * ct));
        float4 bB = __ldg(reinterpret_cast<const float4*>(b_op + 8 * ct + 4));
        const float bv[8] = { bA.x, bA.y, bA.z, bA.w, bB.x, bB.y, bB.z, bB.w };
        float mx[8];
#pragma unroll
        for (int c = 0; c < 8; c++) mx[c] = -FLT_MAX;
#pragma unroll
        for (int p = 0; p < 4; p++) {
            bool vlo = (8 * ktg + 2 * p)     < V;
            bool vhi = (8 * ktg + 2 * p + 1) < V;
#pragma unroll
            for (int c = 0; c < 8; c++) {
                float2 f = *reinterpret_cast<float2*>(&acc[p][c]);
                if (vlo) mx[c] = fmaxf(mx[c], f.x + bv[c]);
                if (vhi) mx[c] = fmaxf(mx[c], f.y + bv[c]);
            }
        }
#pragma unroll
        for (int d = 8; d < 32; d <<= 1)
#pragma unroll
            for (int c = 0; c < 8; c++)
                mx[c] = fmaxf(mx[c], __shfl_xor_sync(0xffffffffu, mx[c], d));
        float z = (V < KK) ? 0.f : -FLT_MAX;   // zero row joins iff a slot invalid
        if (ktg == 0) {                        // lanes 0..7
#pragma unroll
            for (int c = 0; c < 8; c++)
                s_pool[8 * ct + c][wid] = fmaxf(mx[c], z);
        }
    }
    __syncthreads();

    // ---- Phase C: cooperative aggregator, 4 centers share each W_agg read ----
    {
        ull acc01 = dupf(b_agg[tid]);
        ull acc23 = acc01;
#pragma unroll 8
        for (int cc = 0; cc < COP; cc++) {
            ull wd  = dupf(__ldg(&W_agg[(size_t)cc * COUT + tid]));
            ull p01 = *reinterpret_cast<const ull*>(&s_pool[cc][0]);
            ull p23 = *reinterpret_cast<const ull*>(&s_pool[cc][2]);
            ffma2p(acc01, p01, wd);
            ffma2p(acc23, p23, wd);
        }
        float2 r01 = *reinterpret_cast<float2*>(&acc01);
        float2 r23 = *reinterpret_cast<float2*>(&acc23);
        const int mbase = (blockIdx.x * WPC) & (MM - 1);
        size_t obase = ((size_t)b * MM + mbase) * COUT + tid;
        out[obase + 0 * COUT] = fmaxf(r01.x, 0.f);
        out[obase + 1 * COUT] = fmaxf(r01.y, 0.f);
        out[obase + 2 * COUT] = fmaxf(r23.x, 0.f);
        out[obase + 3 * COUT] = fmaxf(r23.y, 0.f);
    }
}

extern "C" void kernel_launch(void* const* d_in, const int* in_sizes, int n_in,
                              void* d_out, int out_size)
{
    (void)in_sizes; (void)n_in; (void)out_size;
    pointnet_sampler_kernel<<<BB * MM / WPC, 128>>>(
        (const float*)d_in[0],  // positions
        (const float*)d_in[1],  // features
        (const float*)d_in[2],  // centers
        (const float*)d_in[3],  // distances
        (const float*)d_in[4],  // W_op
        (const float*)d_in[5],  // b_op
        (const float*)d_in[6],  // W_agg
        (const float*)d_in[7],  // b_agg
        (float*)d_out);
}